// round 6
// baseline (speedup 1.0000x reference)
#include <cuda_runtime.h>
#include <cuda_fp16.h>
#include <cstdint>

#define NUM_EDGE  14
#define NUM_NODES 10000
#define BATCH     8192
#define EDGE_IN   1536
#define HET_IN    1792
#define DOUT      128

__device__ __half g_agg[(size_t)BATCH * HET_IN];
__device__ __half g_WE [(size_t)NUM_EDGE * EDGE_IN * DOUT];
__device__ __half g_WH [(size_t)HET_IN * DOUT];

__device__ __forceinline__ uint32_t f2h2(float x, float y) {
    __half2 h = __floats2half2_rn(x, y);
    return *(uint32_t*)&h;
}

__device__ __forceinline__ void cp16(uint32_t s, const void* g) {
    asm volatile("cp.async.cg.shared.global [%0], [%1], 16;\n" :: "r"(s), "l"(g));
}
__device__ __forceinline__ void cp_commit() { asm volatile("cp.async.commit_group;\n"); }
template <int N> __device__ __forceinline__ void cp_wait() {
    asm volatile("cp.async.wait_group %0;\n" :: "n"(N));
}

__device__ __forceinline__ void ldsm_x4(uint32_t* r, uint32_t a) {
    asm volatile("ldmatrix.sync.aligned.m8n8.x4.shared.b16 {%0,%1,%2,%3}, [%4];"
        : "=r"(r[0]), "=r"(r[1]), "=r"(r[2]), "=r"(r[3]) : "r"(a));
}
__device__ __forceinline__ void ldsm_x4_t(uint32_t* r, uint32_t a) {
    asm volatile("ldmatrix.sync.aligned.m8n8.x4.trans.shared.b16 {%0,%1,%2,%3}, [%4];"
        : "=r"(r[0]), "=r"(r[1]), "=r"(r[2]), "=r"(r[3]) : "r"(a));
}
__device__ __forceinline__ void sts128(uint32_t a, uint32_t x, uint32_t y, uint32_t z, uint32_t w) {
    asm volatile("st.shared.v4.b32 [%0], {%1,%2,%3,%4};" :: "r"(a), "r"(x), "r"(y), "r"(z), "r"(w));
}

__device__ __forceinline__ void mma_f16(float* c, const uint32_t* a, const uint32_t* b) {
    asm volatile(
        "mma.sync.aligned.m16n8k16.row.col.f32.f16.f16.f32 "
        "{%0,%1,%2,%3}, {%4,%5,%6,%7}, {%8,%9}, {%0,%1,%2,%3};\n"
        : "+f"(c[0]), "+f"(c[1]), "+f"(c[2]), "+f"(c[3])
        : "r"(a[0]), "r"(a[1]), "r"(a[2]), "r"(a[3]), "r"(b[0]), "r"(b[1]));
}

__global__ void cvt_to_half(const float4* __restrict__ s, __half2* __restrict__ d, int n4) {
    int i = blockIdx.x * blockDim.x + threadIdx.x;
    if (i < n4) {
        float4 v = s[i];
        d[2 * i]     = __floats2half2_rn(v.x, v.y);
        d[2 * i + 1] = __floats2half2_rn(v.z, v.w);
    }
}

// EDGE=true : BM=128, warp 64x32, A gathered fp32->fp16 at STS, out -> g_agg (fp16).
// EDGE=false: BM=32,  warp 16x32, A = g_agg via cp.async,       out -> final fp32.
// 4-slot smem ring, two 32-wide K-tiles consumed per barrier.
// Schedule invariant: iteration i computes tiles 2i,2i+1 (slots (2i)&3,(2i+1)&3) and
// AFTER the top-of-loop __syncthreads writes tiles 2i+2,2i+3 into slots (2i+2)&3,
// (2i+3)&3 -- exactly the slots consumed at iteration i-1. Prologue fills slots 0,1 only.
template <bool EDGE>
__global__ void __launch_bounds__(256, EDGE ? 2 : 4) hetagg_f16(
    const float* __restrict__ Afeat,
    const int*   __restrict__ gid,
    const float* __restrict__ ball,
    float*       __restrict__ outFinal)
{
    constexpr int BM    = EDGE ? 128 : 32;
    constexpr int WMT   = EDGE ? 4 : 1;
    constexpr int K     = EDGE ? EDGE_IN : HET_IN;
    constexpr int KT    = K / 32;
    constexpr int NI    = KT / 2;
    constexpr int A_ST  = BM * 80;
    constexpr int B_ST  = 32 * 256;
    constexpr int OFF_B = 4 * A_ST;

    extern __shared__ char smem[];
    const uint32_t sb = (uint32_t)__cvta_generic_to_shared(smem);

    const int e    = EDGE ? blockIdx.y : 0;
    const int tid  = threadIdx.x;
    const int l    = tid & 31;
    const int warp = tid >> 5;
    const int wm   = warp >> 2, wn = warp & 3;
    const int m0   = blockIdx.x * BM;

    // ---- B loader: k-row tid>>3 (0..31), two swizzled 16B chunks
    const __half* Bh = EDGE ? (g_WE + (size_t)e * EDGE_IN * DOUT) : g_WH;
    const int bk = tid >> 3;
    const int bc = (tid & 7) * 2;
    const __half* bsrc = Bh + (size_t)bk * DOUT + bc * 8;
    const uint32_t bdst0 = sb + OFF_B + bk * 256 + ((bc >> 3) * 128) + (((bc & 7) ^ (bk & 7)) * 16);
    const int bc1 = bc + 1;
    const uint32_t bdst1 = sb + OFF_B + bk * 256 + ((bc1 >> 3) * 128) + (((bc1 & 7) ^ (bk & 7)) * 16);
    auto cpB = [&](int s, int kt) {
        const __half* src = bsrc + (size_t)kt * 32 * DOUT;
        cp16(bdst0 + s * B_ST, src);
        cp16(bdst1 + s * B_ST, src + 8);
    };

    // ---- A loader
    const float*  agF = nullptr;
    const __half* agH = nullptr;
    uint32_t aSt = 0, adst = 0;
    if (EDGE) {
        const int arow = tid >> 1, ah = tid & 1;
        agF = Afeat + (size_t)e * NUM_NODES * EDGE_IN
                    + (size_t)gid[m0 + arow] * EDGE_IN + ah * 16;
        aSt = sb + arow * 80 + ah * 32;
    } else {
        const int arow = tid >> 2, ac = tid & 3;   // threads 0..127 active
        agH  = g_agg + (size_t)(m0 + arow) * HET_IN + ac * 8;
        adst = sb + arow * 80 + ac * 16;
    }

    float4 av[2][4];   // register prefetch for two A K-tiles (EDGE)
    auto ldA = [&](int b, int kt) {
        const float4* p = (const float4*)(agF + kt * 32);
        av[b][0] = p[0]; av[b][1] = p[1]; av[b][2] = p[2]; av[b][3] = p[3];
    };
    auto stsA = [&](int b, int s) {
        sts128(aSt + s * A_ST,
               f2h2(av[b][0].x, av[b][0].y), f2h2(av[b][0].z, av[b][0].w),
               f2h2(av[b][1].x, av[b][1].y), f2h2(av[b][1].z, av[b][1].w));
        sts128(aSt + s * A_ST + 16,
               f2h2(av[b][2].x, av[b][2].y), f2h2(av[b][2].z, av[b][2].w),
               f2h2(av[b][3].x, av[b][3].y), f2h2(av[b][3].z, av[b][3].w));
    };
    auto cpA = [&](int s, int kt) {
        if (tid < 128) cp16(adst + s * A_ST, agH + kt * 32);
    };

    float acc[WMT][4][4];
    #pragma unroll
    for (int i = 0; i < WMT; ++i)
        #pragma unroll
        for (int j = 0; j < 4; ++j)
            #pragma unroll
            for (int q = 0; q < 4; ++q) acc[i][j][q] = 0.f;

    // ---- prologue: slots 0,1 get tiles 0,1; register-prefetch tiles 2,3 (EDGE)
    if (EDGE) {
        ldA(0, 0); stsA(0, 0); cpB(0, 0); cp_commit();
        ldA(1, 1); stsA(1, 1); cpB(1, 1); cp_commit();
        ldA(0, 2); ldA(1, 3);
    } else {
        cpA(0, 0); cpB(0, 0); cp_commit();
        cpA(1, 1); cpB(1, 1); cp_commit();
    }

    for (int i = 0; i < NI; ++i) {
        cp_wait<0>();        // B (and HET A) of tiles 2i,2i+1 landed
        __syncthreads();     // all warps past iter i-1 -> slots (2i+2)&3,(2i+3)&3 free

        const int k2 = 2 * i + 2;
        if (k2 < KT) {
            if (EDGE) {
                stsA(0, k2 & 3); stsA(1, (k2 + 1) & 3);
                cpB(k2 & 3, k2);           cp_commit();
                cpB((k2 + 1) & 3, k2 + 1); cp_commit();
                if (k2 + 2 < KT) { ldA(0, k2 + 2); ldA(1, k2 + 3); }
            } else {
                cpA(k2 & 3, k2);           cpB(k2 & 3, k2);           cp_commit();
                cpA((k2 + 1) & 3, k2 + 1); cpB((k2 + 1) & 3, k2 + 1); cp_commit();
            }
        }

        // ---- compute tiles 2i, 2i+1 from slots (2i)&3, (2i+1)&3
        #pragma unroll
        for (int h = 0; h < 2; ++h) {
            const int s = (2 * i + h) & 3;
            const uint32_t Ab = sb + s * A_ST;
            const uint32_t Bb = sb + OFF_B + s * B_ST;
            #pragma unroll
            for (int kk = 0; kk < 2; ++kk) {
                uint32_t af[WMT][4];
                #pragma unroll
                for (int mt = 0; mt < WMT; ++mt)
                    ldsm_x4(af[mt], Ab + (wm * (WMT * 16) + mt * 16 + (l & 15)) * 80
                                       + kk * 32 + (l >> 4) * 16);
                uint32_t bf[4][2];
                #pragma unroll
                for (int ntp = 0; ntp < 2; ++ntp) {
                    const int krow = kk * 16 + ((l >> 3) & 1) * 8 + (l & 7);
                    const int c    = wn * 4 + ntp * 2 + (l >> 4);
                    uint32_t r[4];
                    ldsm_x4_t(r, Bb + krow * 256 + ((c >> 3) * 128)
                                 + (((c & 7) ^ (krow & 7)) << 4));
                    bf[2 * ntp][0] = r[0];     bf[2 * ntp][1] = r[1];
                    bf[2 * ntp + 1][0] = r[2]; bf[2 * ntp + 1][1] = r[3];
                }
                #pragma unroll
                for (int mt = 0; mt < WMT; ++mt)
                    #pragma unroll
                    for (int nt = 0; nt < 4; ++nt)
                        mma_f16(acc[mt][nt], af[mt], bf[nt]);
            }
        }
    }

    // ---- epilogue: bias + leaky_relu(0.01)
    const float* bias = EDGE ? (ball + e * DOUT) : ball;
    #pragma unroll
    for (int mt = 0; mt < WMT; ++mt) {
        const int row = m0 + wm * (WMT * 16) + mt * 16 + (l >> 2);
        #pragma unroll
        for (int nt = 0; nt < 4; ++nt) {
            const int col = wn * 32 + nt * 8 + (l & 3) * 2;
            const float2 bv = *(const float2*)&bias[col];
            float x0 = acc[mt][nt][0] + bv.x; x0 = x0 > 0.f ? x0 : 0.01f * x0;
            float x1 = acc[mt][nt][1] + bv.y; x1 = x1 > 0.f ? x1 : 0.01f * x1;
            float x2 = acc[mt][nt][2] + bv.x; x2 = x2 > 0.f ? x2 : 0.01f * x2;
            float x3 = acc[mt][nt][3] + bv.y; x3 = x3 > 0.f ? x3 : 0.01f * x3;
            if (EDGE) {
                *(__half2*)&g_agg[(size_t)row * HET_IN + e * DOUT + col]       = __floats2half2_rn(x0, x1);
                *(__half2*)&g_agg[(size_t)(row + 8) * HET_IN + e * DOUT + col] = __floats2half2_rn(x2, x3);
            } else {
                *(float2*)&outFinal[(size_t)row * DOUT + col]       = make_float2(x0, x1);
                *(float2*)&outFinal[(size_t)(row + 8) * DOUT + col] = make_float2(x2, x3);
            }
        }
    }
}

extern "C" void kernel_launch(void* const* d_in, const int* in_sizes, int n_in,
                              void* d_out, int out_size) {
    const float* features = (const float*)d_in[0];
    const float* W_edge   = (const float*)d_in[1];
    const float* b_edge   = (const float*)d_in[2];
    const float* W_het    = (const float*)d_in[3];
    const float* b_het    = (const float*)d_in[4];
    const int*   gid      = (const int*)d_in[5];
    float* out = (float*)d_out;

    __half* we; cudaGetSymbolAddress((void**)&we, g_WE);
    __half* wh; cudaGetSymbolAddress((void**)&wh, g_WH);

    const int n4e = NUM_EDGE * EDGE_IN * DOUT / 4;
    const int n4h = HET_IN * DOUT / 4;
    cvt_to_half<<<(n4e + 255) / 256, 256>>>((const float4*)W_edge, (__half2*)we, n4e);
    cvt_to_half<<<(n4h + 255) / 256, 256>>>((const float4*)W_het, (__half2*)wh, n4h);

    const int smem1 = 4 * (128 * 80) + 4 * (32 * 256);  // 73728
    const int smem2 = 4 * (32 * 80)  + 4 * (32 * 256);  // 43008

    cudaFuncSetAttribute(hetagg_f16<true>,
                         cudaFuncAttributeMaxDynamicSharedMemorySize, smem1);
    cudaFuncSetAttribute(hetagg_f16<false>,
                         cudaFuncAttributeMaxDynamicSharedMemorySize, smem2);

    dim3 g1(BATCH / 128, NUM_EDGE);
    hetagg_f16<true><<<g1, 256, smem1>>>(features, gid, b_edge, nullptr);

    dim3 g2(BATCH / 32, 1);
    hetagg_f16<false><<<g2, 256, smem2>>>(nullptr, nullptr, b_het, out);
}